// round 1
// baseline (speedup 1.0000x reference)
#include <cuda_runtime.h>

#define NS 100000
#define NT 50000
#define NE 600000
#define CH 128
#define NR 7
#define NTY 4
#define KREL (NR * CH)      // 896... no: 7*128 = 896? careful: 7*128=896
// NOTE: NR*CH = 896, root extension NTY*CH = 512, total K = 1408
#define KTOT (NR * CH + NTY * CH)   // 1408

// ---------------- device scratch (allocation-free contract) ----------------
__device__ float g_agg[(size_t)NT * NR * CH];   // 50000*7*128 fp32 = 179.2 MB
__device__ float g_cnt[NT * NR];                // counts -> reciprocals
__device__ float g_Bt[KTOT * CH];               // stacked transposed weights, 721 KB

// ---------------- f32x2 packed-math helpers (sm_103a) ----------------
__device__ __forceinline__ unsigned long long pk2(float lo, float hi) {
    unsigned long long r;
    asm("mov.b64 %0, {%1, %2};" : "=l"(r) : "f"(lo), "f"(hi));
    return r;
}
__device__ __forceinline__ unsigned long long fma2(unsigned long long a,
                                                   unsigned long long b,
                                                   unsigned long long c) {
    unsigned long long d;
    asm("fma.rn.f32x2 %0, %1, %2, %3;" : "=l"(d) : "l"(a), "l"(b), "l"(c));
    return d;
}
__device__ __forceinline__ void upk2(unsigned long long v, float& lo, float& hi) {
    asm("mov.b64 {%0, %1}, %2;" : "=f"(lo), "=f"(hi) : "l"(v));
}

// ---------------- kernel 1: zero agg + cnt ----------------
__global__ void k_zero() {
    size_t i = (size_t)blockIdx.x * blockDim.x + threadIdx.x;
    const size_t n_agg4 = ((size_t)NT * NR * CH) / 4;   // 11,200,000
    const size_t n_cnt4 = (NT * NR) / 4;                // 87,500  (350000 % 4 == 0)
    float4 z = make_float4(0.f, 0.f, 0.f, 0.f);
    if (i < n_agg4) reinterpret_cast<float4*>(g_agg)[i] = z;
    if (i < n_cnt4) reinterpret_cast<float4*>(g_cnt)[i] = z;
}

// ---------------- kernel 2: build transposed stacked B (K x 128) ----------------
// Bt[k][n]: k in [0, 896)  -> rel_w[r][n][kk],  r = k>>7, kk = k&127
//           k in [896,1408)-> root_w[ty][n][kk]
__global__ void k_bt(const float* __restrict__ rel_w, const float* __restrict__ root_w) {
    int i = blockIdx.x * blockDim.x + threadIdx.x;
    if (i >= KTOT * CH) return;
    int k = i >> 7;
    int n = i & 127;
    float v;
    if (k < NR * CH) {
        int r = k >> 7, kk = k & 127;
        v = rel_w[(size_t)r * CH * CH + (size_t)n * CH + kk];
    } else {
        int j = k - NR * CH;
        int ty = j >> 7, kk = j & 127;
        v = root_w[(size_t)ty * CH * CH + (size_t)n * CH + kk];
    }
    g_Bt[i] = v;
}

// ---------------- kernel 3: edge scatter (warp per edge) ----------------
__global__ void k_scatter(const float* __restrict__ x_src,
                          const int* __restrict__ edge_src,
                          const int* __restrict__ edge_dst,
                          const int* __restrict__ edge_type) {
    int gtid = blockIdx.x * blockDim.x + threadIdx.x;
    int e = gtid >> 5;
    int lane = gtid & 31;
    if (e >= NE) return;
    int src = edge_src[e];
    int dst = edge_dst[e];
    int r   = edge_type[e];
    float4 v = reinterpret_cast<const float4*>(x_src + (size_t)src * CH)[lane];
    float* a = g_agg + ((size_t)dst * NR + r) * CH + lane * 4;
    atomicAdd(a + 0, v.x);
    atomicAdd(a + 1, v.y);
    atomicAdd(a + 2, v.z);
    atomicAdd(a + 3, v.w);
    if (lane == 0) atomicAdd(&g_cnt[(size_t)dst * NR + r], 1.0f);
}

// ---------------- kernel 4: cnt -> 1/max(cnt,1) ----------------
__global__ void k_inv() {
    int i = blockIdx.x * blockDim.x + threadIdx.x;
    if (i < NT * NR) g_cnt[i] = 1.0f / fmaxf(g_cnt[i], 1.0f);
}

// ---------------- kernel 5: GEMM 50000x128 = A(50000x1408) @ Bt(1408x128) ----------------
// BM=128, BN=128, BK=32, 256 threads, per-thread 8x8 via f32x2 pairs.
// A is built on the fly: cols [0,896) = agg * inv(cnt); cols [896,1408) = typed x_target.
#define BM 128
#define BN 128
#define BK 32
#define APITCH 132   // 128 + 4 pad -> 4-way store conflict, conflict-free f4 reads

__global__ __launch_bounds__(256) void k_gemm(const float* __restrict__ x_target,
                                              const int* __restrict__ tgt_type,
                                              const float* __restrict__ root_b,
                                              float* __restrict__ out) {
    __shared__ float As[BK][APITCH];
    __shared__ float Bs[BK][BN];

    const int tid = threadIdx.x;
    const int tc = tid & 15;          // 16 col groups
    const int tr = tid >> 4;          // 16 row groups
    const int m0 = tr * 8;
    const int n0 = tc * 8;
    const int t0 = blockIdx.x * BM;

    unsigned long long acc[8][4];
    #pragma unroll
    for (int m = 0; m < 8; m++)
        #pragma unroll
        for (int p = 0; p < 4; p++) acc[m][p] = 0ull;  // bits of (+0.f, +0.f)

    const int lk = tid & 31;          // A-load k lane (coalesced over agg row)
    const int lt = tid >> 5;          // A-load row group (0..7)
    const int n4 = tid & 31;          // B-load float4 col
    const int kr = tid >> 5;          // B-load row group (0..7)

    for (int kt = 0; kt < KTOT / BK; kt++) {
        const int k0 = kt * BK;
        // ---- load A tile (built on the fly) ----
        const bool isRoot = (k0 >= NR * CH);
        const int rblk = (isRoot ? (k0 - NR * CH) : k0) >> 7;   // uniform per tile
        const int kk = (k0 & 127) + lk;
        #pragma unroll
        for (int i = 0; i < 16; i++) {
            int tl = lt + i * 8;
            int t = t0 + tl;
            float v = 0.f;
            if (t < NT) {
                if (!isRoot) {
                    size_t base = (size_t)t * NR + rblk;
                    v = g_agg[base * CH + kk] * g_cnt[base];
                } else {
                    if (tgt_type[t] == rblk) v = x_target[(size_t)t * CH + kk];
                }
            }
            As[lk][tl] = v;
        }
        // ---- load B tile ----
        #pragma unroll
        for (int i = 0; i < 4; i++) {
            int kkb = kr + i * 8;
            reinterpret_cast<float4*>(&Bs[kkb][0])[n4] =
                reinterpret_cast<const float4*>(g_Bt)[(size_t)(k0 + kkb) * (CH / 4) + n4];
        }
        __syncthreads();

        // ---- compute ----
        #pragma unroll 8
        for (int k = 0; k < BK; k++) {
            float4 a0 = *reinterpret_cast<const float4*>(&As[k][m0]);
            float4 a1 = *reinterpret_cast<const float4*>(&As[k][m0 + 4]);
            float4 b0 = *reinterpret_cast<const float4*>(&Bs[k][n0]);
            float4 b1 = *reinterpret_cast<const float4*>(&Bs[k][n0 + 4]);
            unsigned long long bp[4] = { pk2(b0.x, b0.y), pk2(b0.z, b0.w),
                                         pk2(b1.x, b1.y), pk2(b1.z, b1.w) };
            float am[8] = {a0.x, a0.y, a0.z, a0.w, a1.x, a1.y, a1.z, a1.w};
            #pragma unroll
            for (int m = 0; m < 8; m++) {
                unsigned long long ad = pk2(am[m], am[m]);
                #pragma unroll
                for (int p = 0; p < 4; p++) acc[m][p] = fma2(ad, bp[p], acc[m][p]);
            }
        }
        __syncthreads();
    }

    // ---- epilogue: add per-type bias, write out ----
    #pragma unroll
    for (int i = 0; i < 8; i++) {
        int t = t0 + m0 + i;
        if (t >= NT) break;
        int ty = tgt_type[t];
        const float4* rb = reinterpret_cast<const float4*>(root_b + (size_t)ty * CH + n0);
        float4 bb0 = rb[0], bb1 = rb[1];
        float v0, v1, v2, v3, v4, v5, v6, v7;
        upk2(acc[i][0], v0, v1);
        upk2(acc[i][1], v2, v3);
        upk2(acc[i][2], v4, v5);
        upk2(acc[i][3], v6, v7);
        float4 w0 = make_float4(v0 + bb0.x, v1 + bb0.y, v2 + bb0.z, v3 + bb0.w);
        float4 w1 = make_float4(v4 + bb1.x, v5 + bb1.y, v6 + bb1.z, v7 + bb1.w);
        float4* op = reinterpret_cast<float4*>(out + (size_t)t * CH + n0);
        op[0] = w0;
        op[1] = w1;
    }
}

// ---------------- launch ----------------
extern "C" void kernel_launch(void* const* d_in, const int* in_sizes, int n_in,
                              void* d_out, int out_size) {
    const float* x_src     = (const float*)d_in[0];
    const float* x_target  = (const float*)d_in[1];
    const float* rel_w     = (const float*)d_in[2];
    const float* root_w    = (const float*)d_in[3];
    const float* root_b    = (const float*)d_in[4];
    const int*   edge_src  = (const int*)d_in[5];
    const int*   edge_dst  = (const int*)d_in[6];
    const int*   edge_type = (const int*)d_in[7];
    const int*   tgt_type  = (const int*)d_in[8];
    float* out = (float*)d_out;

    (void)in_sizes; (void)n_in; (void)out_size;

    // zero 179 MB agg + counts
    {
        size_t n4 = ((size_t)NT * NR * CH) / 4;
        int blocks = (int)((n4 + 255) / 256);
        k_zero<<<blocks, 256>>>();
    }
    // stacked transposed weights
    k_bt<<<(KTOT * CH + 255) / 256, 256>>>(rel_w, root_w);
    // edge scatter: 8 edges (warps) per 256-thread block
    k_scatter<<<(NE + 7) / 8, 256>>>(x_src, edge_src, edge_dst, edge_type);
    // reciprocal counts
    k_inv<<<(NT * NR + 255) / 256, 256>>>();
    // fused GEMM (relations + typed root) + bias epilogue
    k_gemm<<<(NT + BM - 1) / BM, 256>>>(x_target, tgt_type, root_b, out);
}

// round 2
// speedup vs baseline: 1.0973x; 1.0973x over previous
#include <cuda_runtime.h>

#define NS 100000
#define NT 50000
#define NE 600000
#define CH 128
#define NR 7
#define NTY 4
#define KTOT (NR * CH + NTY * CH)   // 896 + 512 = 1408

// ---------------- device scratch (allocation-free contract) ----------------
__device__ float g_agg[(size_t)NT * NR * CH];   // 179.2 MB
__device__ float g_cnt[NT * NR];                // counts -> reciprocals
__device__ float g_Bt[KTOT * CH];               // stacked transposed weights, 721 KB

// ---------------- f32x2 packed-math helpers (sm_103a) ----------------
__device__ __forceinline__ unsigned long long pk2(float lo, float hi) {
    unsigned long long r;
    asm("mov.b64 %0, {%1, %2};" : "=l"(r) : "f"(lo), "f"(hi));
    return r;
}
__device__ __forceinline__ unsigned long long fma2(unsigned long long a,
                                                   unsigned long long b,
                                                   unsigned long long c) {
    unsigned long long d;
    asm("fma.rn.f32x2 %0, %1, %2, %3;" : "=l"(d) : "l"(a), "l"(b), "l"(c));
    return d;
}
__device__ __forceinline__ void upk2(unsigned long long v, float& lo, float& hi) {
    asm("mov.b64 {%0, %1}, %2;" : "=f"(lo), "=f"(hi) : "l"(v));
}

// ---------------- kernel 1: fused zero(agg,cnt) + build Bt ----------------
// Bt[k][n]: k in [0, 896)  -> rel_w[r][n][kk],  r = k>>7, kk = k&127
//           k in [896,1408)-> root_w[ty][n][kk]
__global__ void k_init(const float* __restrict__ rel_w, const float* __restrict__ root_w) {
    size_t i = (size_t)blockIdx.x * blockDim.x + threadIdx.x;
    const size_t n_agg4 = ((size_t)NT * NR * CH) / 4;   // 11,200,000
    const size_t n_cnt4 = (NT * NR) / 4;                // 87,500
    float4 z = make_float4(0.f, 0.f, 0.f, 0.f);
    if (i < n_agg4) reinterpret_cast<float4*>(g_agg)[i] = z;
    if (i < n_cnt4) reinterpret_cast<float4*>(g_cnt)[i] = z;
    if (i < KTOT * CH) {
        int k = (int)(i >> 7);
        int n = (int)(i & 127);
        float v;
        if (k < NR * CH) {
            int r = k >> 7, kk = k & 127;
            v = rel_w[(size_t)r * CH * CH + (size_t)n * CH + kk];
        } else {
            int j = k - NR * CH;
            int ty = j >> 7, kk = j & 127;
            v = root_w[(size_t)ty * CH * CH + (size_t)n * CH + kk];
        }
        g_Bt[i] = v;
    }
}

// ---------------- kernel 2: edge scatter (warp per edge, red.v4) ----------------
__global__ void k_scatter(const float* __restrict__ x_src,
                          const int* __restrict__ edge_src,
                          const int* __restrict__ edge_dst,
                          const int* __restrict__ edge_type) {
    int gtid = blockIdx.x * blockDim.x + threadIdx.x;
    int e = gtid >> 5;
    int lane = gtid & 31;
    if (e >= NE) return;
    int src = edge_src[e];
    int dst = edge_dst[e];
    int r   = edge_type[e];
    float4 v = reinterpret_cast<const float4*>(x_src + (size_t)src * CH)[lane];
    float* a = g_agg + ((size_t)dst * NR + r) * CH + lane * 4;
    asm volatile("red.global.add.v4.f32 [%0], {%1, %2, %3, %4};"
                 :: "l"(a), "f"(v.x), "f"(v.y), "f"(v.z), "f"(v.w)
                 : "memory");
    if (lane == 0) {
        float* c = &g_cnt[(size_t)dst * NR + r];
        asm volatile("red.global.add.f32 [%0], %1;" :: "l"(c), "f"(1.0f) : "memory");
    }
}

// ---------------- kernel 3: cnt -> 1/max(cnt,1) ----------------
__global__ void k_inv() {
    int i = blockIdx.x * blockDim.x + threadIdx.x;
    if (i < NT * NR) g_cnt[i] = 1.0f / fmaxf(g_cnt[i], 1.0f);
}

// ---------------- kernel 4: GEMM 50000x128 = A(50000x1408) @ Bt(1408x128) ----------------
#define BM 128
#define BN 128
#define BK 32
#define APITCH 132

__global__ __launch_bounds__(256) void k_gemm(const float* __restrict__ x_target,
                                              const int* __restrict__ tgt_type,
                                              const float* __restrict__ root_b,
                                              float* __restrict__ out) {
    __shared__ float As[BK][APITCH];
    __shared__ float Bs[BK][BN];

    const int tid = threadIdx.x;
    const int tc = tid & 15;
    const int tr = tid >> 4;
    const int m0 = tr * 8;
    const int n0 = tc * 8;
    const int t0 = blockIdx.x * BM;

    unsigned long long acc[8][4];
    #pragma unroll
    for (int m = 0; m < 8; m++)
        #pragma unroll
        for (int p = 0; p < 4; p++) acc[m][p] = 0ull;

    const int lk = tid & 31;
    const int lt = tid >> 5;
    const int n4 = tid & 31;
    const int kr = tid >> 5;

    for (int kt = 0; kt < KTOT / BK; kt++) {
        const int k0 = kt * BK;
        const bool isRoot = (k0 >= NR * CH);
        const int rblk = (isRoot ? (k0 - NR * CH) : k0) >> 7;
        const int kk = (k0 & 127) + lk;
        #pragma unroll
        for (int i = 0; i < 16; i++) {
            int tl = lt + i * 8;
            int t = t0 + tl;
            float v = 0.f;
            if (t < NT) {
                if (!isRoot) {
                    size_t base = (size_t)t * NR + rblk;
                    v = g_agg[base * CH + kk] * g_cnt[base];
                } else {
                    if (tgt_type[t] == rblk) v = x_target[(size_t)t * CH + kk];
                }
            }
            As[lk][tl] = v;
        }
        #pragma unroll
        for (int i = 0; i < 4; i++) {
            int kkb = kr + i * 8;
            reinterpret_cast<float4*>(&Bs[kkb][0])[n4] =
                reinterpret_cast<const float4*>(g_Bt)[(size_t)(k0 + kkb) * (CH / 4) + n4];
        }
        __syncthreads();

        #pragma unroll 8
        for (int k = 0; k < BK; k++) {
            float4 a0 = *reinterpret_cast<const float4*>(&As[k][m0]);
            float4 a1 = *reinterpret_cast<const float4*>(&As[k][m0 + 4]);
            float4 b0 = *reinterpret_cast<const float4*>(&Bs[k][n0]);
            float4 b1 = *reinterpret_cast<const float4*>(&Bs[k][n0 + 4]);
            unsigned long long bp[4] = { pk2(b0.x, b0.y), pk2(b0.z, b0.w),
                                         pk2(b1.x, b1.y), pk2(b1.z, b1.w) };
            float am[8] = {a0.x, a0.y, a0.z, a0.w, a1.x, a1.y, a1.z, a1.w};
            #pragma unroll
            for (int m = 0; m < 8; m++) {
                unsigned long long ad = pk2(am[m], am[m]);
                #pragma unroll
                for (int p = 0; p < 4; p++) acc[m][p] = fma2(ad, bp[p], acc[m][p]);
            }
        }
        __syncthreads();
    }

    #pragma unroll
    for (int i = 0; i < 8; i++) {
        int t = t0 + m0 + i;
        if (t >= NT) break;
        int ty = tgt_type[t];
        const float4* rb = reinterpret_cast<const float4*>(root_b + (size_t)ty * CH + n0);
        float4 bb0 = rb[0], bb1 = rb[1];
        float v0, v1, v2, v3, v4, v5, v6, v7;
        upk2(acc[i][0], v0, v1);
        upk2(acc[i][1], v2, v3);
        upk2(acc[i][2], v4, v5);
        upk2(acc[i][3], v6, v7);
        float4 w0 = make_float4(v0 + bb0.x, v1 + bb0.y, v2 + bb0.z, v3 + bb0.w);
        float4 w1 = make_float4(v4 + bb1.x, v5 + bb1.y, v6 + bb1.z, v7 + bb1.w);
        float4* op = reinterpret_cast<float4*>(out + (size_t)t * CH + n0);
        op[0] = w0;
        op[1] = w1;
    }
}

// ---------------- launch ----------------
extern "C" void kernel_launch(void* const* d_in, const int* in_sizes, int n_in,
                              void* d_out, int out_size) {
    const float* x_src     = (const float*)d_in[0];
    const float* x_target  = (const float*)d_in[1];
    const float* rel_w     = (const float*)d_in[2];
    const float* root_w    = (const float*)d_in[3];
    const float* root_b    = (const float*)d_in[4];
    const int*   edge_src  = (const int*)d_in[5];
    const int*   edge_dst  = (const int*)d_in[6];
    const int*   edge_type = (const int*)d_in[7];
    const int*   tgt_type  = (const int*)d_in[8];
    float* out = (float*)d_out;

    (void)in_sizes; (void)n_in; (void)out_size;

    // fused zero + weight-stack build
    {
        size_t n4 = ((size_t)NT * NR * CH) / 4;
        int blocks = (int)((n4 + 255) / 256);
        k_init<<<blocks, 256>>>(rel_w, root_w);
    }
    // edge scatter: warp per edge, red.v4
    k_scatter<<<(NE + 7) / 8, 256>>>(x_src, edge_src, edge_dst, edge_type);
    // reciprocal counts
    k_inv<<<(NT * NR + 255) / 256, 256>>>();
    // fused GEMM (relations + typed root) + bias epilogue
    k_gemm<<<(NT + BM - 1) / BM, 256>>>(x_target, tgt_type, root_b, out);
}

// round 5
// speedup vs baseline: 1.1880x; 1.0827x over previous
#include <cuda_runtime.h>
#include <cuda_bf16.h>
#include <cstdint>

#define NS 100000
#define NT 50000
#define NE 600000
#define CH 128
#define NR 7
#define NTY 4
#define KREL (NR * CH)              // 896
#define KORIG (NR * CH + NTY * CH)  // 1408
#define NGRP (KORIG / 8)            // 176 groups of 8 orig-k
#define NITER (KORIG / 16)          // 88 iters; 16 orig-k -> 48 expanded bf16

// ---------------- device scratch ----------------
__device__ float g_agg[(size_t)NT * NR * CH];       // 179.2 MB
__device__ float g_cnt[NT * NR];                    // counts -> reciprocals
// B expanded 3-term layout: row n (128), per group g (176): [bh x8][bh x8][bl x8] = 12 u32
__device__ unsigned g_B3[128 * NGRP * 12];          // 1.08 MB

// ---------------- helpers ----------------
__device__ __forceinline__ uint32_t smem_u32(const void* p) {
    uint32_t a;
    asm("{ .reg .u64 t; cvta.to.shared.u64 t, %1; cvt.u32.u64 %0, t; }" : "=r"(a) : "l"(p));
    return a;
}
static __device__ __forceinline__ void split2(float a, uint16_t& h, uint16_t& l) {
    __nv_bfloat16 hb = __float2bfloat16_rn(a);
    float hf = __bfloat162float(hb);
    __nv_bfloat16 lb = __float2bfloat16_rn(a - hf);
    h = __bfloat16_as_ushort(hb);
    l = __bfloat16_as_ushort(lb);
}
__device__ __forceinline__ void ldsm4(uint32_t* r, uint32_t addr) {
    asm volatile("ldmatrix.sync.aligned.m8n8.x4.shared.b16 {%0,%1,%2,%3}, [%4];"
                 : "=r"(r[0]), "=r"(r[1]), "=r"(r[2]), "=r"(r[3]) : "r"(addr));
}
__device__ __forceinline__ void mma16816(float* d, const uint32_t* a, const uint32_t* b) {
    asm volatile("mma.sync.aligned.m16n8k16.row.col.f32.bf16.bf16.f32 "
                 "{%0,%1,%2,%3}, {%4,%5,%6,%7}, {%8,%9}, {%0,%1,%2,%3};"
                 : "+f"(d[0]), "+f"(d[1]), "+f"(d[2]), "+f"(d[3])
                 : "r"(a[0]), "r"(a[1]), "r"(a[2]), "r"(a[3]), "r"(b[0]), "r"(b[1]));
}

// ---------------- kernel 1: zero agg/cnt + build 3-term expanded B ----------------
__global__ void k_init(const float* __restrict__ rel_w, const float* __restrict__ root_w) {
    size_t i = (size_t)blockIdx.x * blockDim.x + threadIdx.x;
    const size_t n_agg4 = ((size_t)NT * NR * CH) / 4;
    const size_t n_cnt4 = (NT * NR) / 4;
    float4 z = make_float4(0.f, 0.f, 0.f, 0.f);
    if (i < n_agg4) reinterpret_cast<float4*>(g_agg)[i] = z;
    if (i < n_cnt4) reinterpret_cast<float4*>(g_cnt)[i] = z;
    if (i < (size_t)128 * NGRP) {
        int n = (int)(i / NGRP);
        int g = (int)(i % NGRP);
        uint32_t bh[4], bl[4];
        #pragma unroll
        for (int jp = 0; jp < 4; jp++) {
            uint16_t h0, l0, h1, l1;
            #pragma unroll
            for (int s = 0; s < 2; s++) {
                int kg = g * 8 + jp * 2 + s;
                float w;
                if (kg < KREL) {
                    int r = kg >> 7, kk = kg & 127;
                    w = rel_w[(size_t)r * CH * CH + (size_t)n * CH + kk];
                } else {
                    int j = kg - KREL;
                    int ty = j >> 7, kk = j & 127;
                    w = root_w[(size_t)ty * CH * CH + (size_t)n * CH + kk];
                }
                if (s == 0) split2(w, h0, l0); else split2(w, h1, l1);
            }
            bh[jp] = (uint32_t)h0 | ((uint32_t)h1 << 16);
            bl[jp] = (uint32_t)l0 | ((uint32_t)l1 << 16);
        }
        unsigned* dst = g_B3 + i * 12;
        uint4* d4 = reinterpret_cast<uint4*>(dst);
        d4[0] = make_uint4(bh[0], bh[1], bh[2], bh[3]);   // tile0 = bh
        d4[1] = make_uint4(bh[0], bh[1], bh[2], bh[3]);   // tile1 = bh
        d4[2] = make_uint4(bl[0], bl[1], bl[2], bl[3]);   // tile2 = bl
    }
}

// ---------------- kernel 2: edge scatter (warp per edge, red.v4) ----------------
__global__ void k_scatter(const float* __restrict__ x_src,
                          const int* __restrict__ edge_src,
                          const int* __restrict__ edge_dst,
                          const int* __restrict__ edge_type) {
    int gtid = blockIdx.x * blockDim.x + threadIdx.x;
    int e = gtid >> 5;
    int lane = gtid & 31;
    if (e >= NE) return;
    int src = edge_src[e];
    int dst = edge_dst[e];
    int r   = edge_type[e];
    float4 v = reinterpret_cast<const float4*>(x_src + (size_t)src * CH)[lane];
    float* a = g_agg + ((size_t)dst * NR + r) * CH + lane * 4;
    asm volatile("red.global.add.v4.f32 [%0], {%1, %2, %3, %4};"
                 :: "l"(a), "f"(v.x), "f"(v.y), "f"(v.z), "f"(v.w) : "memory");
    if (lane == 0) {
        float* c = &g_cnt[(size_t)dst * NR + r];
        asm volatile("red.global.add.f32 [%0], %1;" :: "l"(c), "f"(1.0f) : "memory");
    }
}

// ---------------- kernel 3: cnt -> 1/max(cnt,1) ----------------
__global__ void k_inv() {
    int i = blockIdx.x * blockDim.x + threadIdx.x;
    if (i < NT * NR) g_cnt[i] = 1.0f / fmaxf(g_cnt[i], 1.0f);
}

// ---------------- kernel 4: mma.sync bf16x3-split GEMM ----------------
// Per iter: 16 orig-k -> 48 expanded bf16 = 96 B/row payload, 112 B pitch.
// Block: BM=64, BN=128, 8 warps (2m x 4n), warp tile 32x32, 3 mma-k16 steps/iter.
#define PITCH 112
#define SM_ABUF (64 * PITCH)     // 7168
#define SM_BBUF (128 * PITCH)    // 14336
#define SM_TOT  (2 * SM_ABUF + 2 * SM_BBUF)   // 43008

__global__ void __launch_bounds__(256) k_gemm_mma(const float* __restrict__ x_target,
                                                  const int* __restrict__ tgt_type,
                                                  const float* __restrict__ root_b,
                                                  float* __restrict__ out) {
    __shared__ __align__(16) char smem[SM_TOT];
    const uint32_t sb = smem_u32(smem);
    const int tid = threadIdx.x;
    const int lane = tid & 31;
    const int wid = tid >> 5;
    const int wm = wid >> 2;      // 0..1
    const int wn = wid & 3;       // 0..3
    const int t0 = blockIdx.x * 64;

    // ---- fill roles: A 64 rows x 4 threads (4 orig-k each); B 128 rows x 2 threads ----
    const int arow = tid >> 2;
    const int q    = tid & 3;           // group g=q>>1, half h=q&1
    const int ag   = q >> 1;
    const int ah_  = q & 1;
    const int brow = tid >> 1;
    const int bhf  = tid & 1;
    const int t = t0 + arow;
    const bool rv = (t < NT);
    const int myty = rv ? tgt_type[t] : -1;
    const float* xrow = x_target + (size_t)t * CH;

    // ---- ldmatrix address components ----
    const int a_row  = wm * 32 + (lane & 15);
    const int a_colb = (lane >> 4) * 16;
    const int b_row  = wn * 32 + ((lane >> 4) << 3) + (lane & 7);
    const int b_colb = ((lane >> 3) & 1) * 16;

    float acc[2][4][4];
    #pragma unroll
    for (int m = 0; m < 2; m++)
        #pragma unroll
        for (int n = 0; n < 4; n++)
            #pragma unroll
            for (int j = 0; j < 4; j++) acc[m][n][j] = 0.f;

    float4 av;
    uint4 bv[3];

    auto loadAB = [&](int i) {
        const int k0 = i * 16;
        const uint4* bp = reinterpret_cast<const uint4*>(
            g_B3 + ((size_t)brow * NGRP + (k0 >> 3) + bhf) * 12);
        bv[0] = bp[0]; bv[1] = bp[1]; bv[2] = bp[2];
        if (k0 < KREL) {
            const int rblk = k0 >> 7;
            if (rv) {
                const size_t base = (size_t)t * NR + rblk;
                const float inv = g_cnt[base];
                float4 v = *reinterpret_cast<const float4*>(
                    g_agg + base * CH + (k0 & 127) + q * 4);
                av = make_float4(v.x * inv, v.y * inv, v.z * inv, v.w * inv);
            } else av = make_float4(0.f, 0.f, 0.f, 0.f);
        } else {
            const int rblk = (k0 - KREL) >> 7;
            if (rv && myty == rblk)
                av = *reinterpret_cast<const float4*>(xrow + (k0 & 127) + q * 4);
            else av = make_float4(0.f, 0.f, 0.f, 0.f);
        }
    };

    loadAB(0);

    for (int i = 0; i < NITER; i++) {
        const int b = i & 1;
        char* Ab = smem + b * SM_ABUF;
        char* Bb = smem + 2 * SM_ABUF + b * SM_BBUF;

        // ---- store prefetched regs -> smem buffer b ----
        {
            uint16_t h0, l0, h1, l1, h2, l2, h3, l3;
            split2(av.x, h0, l0); split2(av.y, h1, l1);
            split2(av.z, h2, l2); split2(av.w, h3, l3);
            uint2 hp = make_uint2((uint32_t)h0 | ((uint32_t)h1 << 16),
                                  (uint32_t)h2 | ((uint32_t)h3 << 16));
            uint2 lp = make_uint2((uint32_t)l0 | ((uint32_t)l1 << 16),
                                  (uint32_t)l2 | ((uint32_t)l3 << 16));
            char* rbase = Ab + arow * PITCH + ag * 48 + ah_ * 8;
            *reinterpret_cast<uint2*>(rbase +  0) = hp;   // tile0 = ah
            *reinterpret_cast<uint2*>(rbase + 16) = lp;   // tile1 = al
            *reinterpret_cast<uint2*>(rbase + 32) = hp;   // tile2 = ah
        }
        {
            char* rbase = Bb + brow * PITCH + bhf * 48;
            uint4* d4 = reinterpret_cast<uint4*>(rbase);
            d4[0] = bv[0]; d4[1] = bv[1]; d4[2] = bv[2];
        }
        __syncthreads();

        if (i + 1 < NITER) loadAB(i + 1);

        // ---- compute from buffer b: 3 k16 steps over 48 expanded k ----
        const uint32_t Au = sb + b * SM_ABUF;
        const uint32_t Bu = sb + 2 * SM_ABUF + b * SM_BBUF;
        #pragma unroll
        for (int ks = 0; ks < 3; ks++) {
            uint32_t af[2][4], bf[2][4];
            #pragma unroll
            for (int mt = 0; mt < 2; mt++)
                ldsm4(af[mt], Au + (a_row + mt * 16) * PITCH + a_colb + ks * 32);
            #pragma unroll
            for (int nt = 0; nt < 2; nt++)
                ldsm4(bf[nt], Bu + (b_row + nt * 16) * PITCH + b_colb + ks * 32);
            #pragma unroll
            for (int mt = 0; mt < 2; mt++)
                #pragma unroll
                for (int nt = 0; nt < 2; nt++) {
                    mma16816(acc[mt][2 * nt],     af[mt], &bf[nt][0]);
                    mma16816(acc[mt][2 * nt + 1], af[mt], &bf[nt][2]);
                }
        }
        __syncthreads();
    }

    // ---- epilogue: d-frag scatter + per-type bias ----
    const int g  = lane >> 2;
    const int tg = lane & 3;
    #pragma unroll
    for (int mt = 0; mt < 2; mt++) {
        const int r0 = t0 + wm * 32 + mt * 16 + g;
        const int r1 = r0 + 8;
        const bool v0 = (r0 < NT), v1 = (r1 < NT);
        const int ty0 = v0 ? tgt_type[r0] : 0;
        const int ty1 = v1 ? tgt_type[r1] : 0;
        const float* rb0 = root_b + (size_t)ty0 * CH;
        const float* rb1 = root_b + (size_t)ty1 * CH;
        #pragma unroll
        for (int nt = 0; nt < 4; nt++) {
            const int col = wn * 32 + nt * 8 + tg * 2;
            if (v0) {
                float2 bb = *reinterpret_cast<const float2*>(rb0 + col);
                float2 w = make_float2(acc[mt][nt][0] + bb.x, acc[mt][nt][1] + bb.y);
                *reinterpret_cast<float2*>(out + (size_t)r0 * CH + col) = w;
            }
            if (v1) {
                float2 bb = *reinterpret_cast<const float2*>(rb1 + col);
                float2 w = make_float2(acc[mt][nt][2] + bb.x, acc[mt][nt][3] + bb.y);
                *reinterpret_cast<float2*>(out + (size_t)r1 * CH + col) = w;
            }
        }
    }
}

// ---------------- launch ----------------
extern "C" void kernel_launch(void* const* d_in, const int* in_sizes, int n_in,
                              void* d_out, int out_size) {
    const float* x_src     = (const float*)d_in[0];
    const float* x_target  = (const float*)d_in[1];
    const float* rel_w     = (const float*)d_in[2];
    const float* root_w    = (const float*)d_in[3];
    const float* root_b    = (const float*)d_in[4];
    const int*   edge_src  = (const int*)d_in[5];
    const int*   edge_dst  = (const int*)d_in[6];
    const int*   edge_type = (const int*)d_in[7];
    const int*   tgt_type  = (const int*)d_in[8];
    float* out = (float*)d_out;

    (void)in_sizes; (void)n_in; (void)out_size;

    {
        size_t n4 = ((size_t)NT * NR * CH) / 4;
        int blocks = (int)((n4 + 255) / 256);
        k_init<<<blocks, 256>>>(rel_w, root_w);
    }
    k_scatter<<<(NE + 7) / 8, 256>>>(x_src, edge_src, edge_dst, edge_type);
    k_inv<<<(NT * NR + 255) / 256, 256>>>();
    k_gemm_mma<<<(NT + 63) / 64, 256>>>(x_target, tgt_type, root_b, out);
}

// round 6
// speedup vs baseline: 2.2135x; 1.8632x over previous
#include <cuda_runtime.h>
#include <cuda_bf16.h>
#include <cstdint>

#define NS 100000
#define NT 50000
#define NE 600000
#define CH 128
#define NR 7
#define NTY 4
#define KREL (NR * CH)              // 896
#define KORIG (NR * CH + NTY * CH)  // 1408
#define NITER (KORIG / 16)          // 88 iters of 16 orig-k

// ---------------- device scratch ----------------
__device__ float g_agg[(size_t)NT * NR * CH];   // 179.2 MB
__device__ float g_cnt[NT * NR];
// B split layout: per row n (128), per 16-k group g (88): [bh x16 (32B)][bl x16 (32B)]
__device__ unsigned g_B2[128 * NITER * 16];     // 721 KB

// ---------------- helpers ----------------
__device__ __forceinline__ uint32_t smem_u32(const void* p) {
    uint32_t a;
    asm("{ .reg .u64 t; cvta.to.shared.u64 t, %1; cvt.u32.u64 %0, t; }" : "=r"(a) : "l"(p));
    return a;
}
static __device__ __forceinline__ void split2(float a, uint16_t& h, uint16_t& l) {
    __nv_bfloat16 hb = __float2bfloat16_rn(a);
    float hf = __bfloat162float(hb);
    __nv_bfloat16 lb = __float2bfloat16_rn(a - hf);
    h = __bfloat16_as_ushort(hb);
    l = __bfloat16_as_ushort(lb);
}
__device__ __forceinline__ void ldsm4(uint32_t* r, uint32_t addr) {
    asm volatile("ldmatrix.sync.aligned.m8n8.x4.shared.b16 {%0,%1,%2,%3}, [%4];"
                 : "=r"(r[0]), "=r"(r[1]), "=r"(r[2]), "=r"(r[3]) : "r"(addr));
}
__device__ __forceinline__ void mma16816(float* d, const uint32_t* a, const uint32_t* b) {
    asm volatile("mma.sync.aligned.m16n8k16.row.col.f32.bf16.bf16.f32 "
                 "{%0,%1,%2,%3}, {%4,%5,%6,%7}, {%8,%9}, {%0,%1,%2,%3};"
                 : "+f"(d[0]), "+f"(d[1]), "+f"(d[2]), "+f"(d[3])
                 : "r"(a[0]), "r"(a[1]), "r"(a[2]), "r"(a[3]), "r"(b[0]), "r"(b[1]));
}
__device__ __forceinline__ void cpasync16(uint32_t dst, const void* src) {
    asm volatile("cp.async.cg.shared.global [%0], [%1], 16;" :: "r"(dst), "l"(src) : "memory");
}
#define CP_COMMIT() asm volatile("cp.async.commit_group;" ::: "memory")
#define CP_WAIT0()  asm volatile("cp.async.wait_group 0;" ::: "memory")

// ---------------- kernel 1: zero agg/cnt + build split B ----------------
__global__ void k_init(const float* __restrict__ rel_w, const float* __restrict__ root_w) {
    size_t i = (size_t)blockIdx.x * blockDim.x + threadIdx.x;
    const size_t n_agg4 = ((size_t)NT * NR * CH) / 4;
    const size_t n_cnt4 = (NT * NR) / 4;
    float4 z = make_float4(0.f, 0.f, 0.f, 0.f);
    if (i < n_agg4) reinterpret_cast<float4*>(g_agg)[i] = z;
    if (i < n_cnt4) reinterpret_cast<float4*>(g_cnt)[i] = z;
    if (i < (size_t)128 * NITER) {
        int n = (int)(i / NITER);
        int g = (int)(i % NITER);
        uint32_t bh[8], bl[8];
        #pragma unroll
        for (int jp = 0; jp < 8; jp++) {
            uint16_t h0, l0, h1, l1;
            #pragma unroll
            for (int s = 0; s < 2; s++) {
                int kg = g * 16 + jp * 2 + s;
                float w;
                if (kg < KREL) {
                    int r = kg >> 7, kk = kg & 127;
                    w = rel_w[(size_t)r * CH * CH + (size_t)n * CH + kk];
                } else {
                    int j = kg - KREL;
                    int ty = j >> 7, kk = j & 127;
                    w = root_w[(size_t)ty * CH * CH + (size_t)n * CH + kk];
                }
                if (s == 0) split2(w, h0, l0); else split2(w, h1, l1);
            }
            bh[jp] = (uint32_t)h0 | ((uint32_t)h1 << 16);
            bl[jp] = (uint32_t)l0 | ((uint32_t)l1 << 16);
        }
        uint4* d4 = reinterpret_cast<uint4*>(g_B2 + i * 16);
        d4[0] = make_uint4(bh[0], bh[1], bh[2], bh[3]);
        d4[1] = make_uint4(bh[4], bh[5], bh[6], bh[7]);
        d4[2] = make_uint4(bl[0], bl[1], bl[2], bl[3]);
        d4[3] = make_uint4(bl[4], bl[5], bl[6], bl[7]);
    }
}

// ---------------- kernel 2: edge scatter ----------------
__global__ void k_scatter(const float* __restrict__ x_src,
                          const int* __restrict__ edge_src,
                          const int* __restrict__ edge_dst,
                          const int* __restrict__ edge_type) {
    int gtid = blockIdx.x * blockDim.x + threadIdx.x;
    int e = gtid >> 5;
    int lane = gtid & 31;
    if (e >= NE) return;
    int src = edge_src[e];
    int dst = edge_dst[e];
    int r   = edge_type[e];
    float4 v = reinterpret_cast<const float4*>(x_src + (size_t)src * CH)[lane];
    float* a = g_agg + ((size_t)dst * NR + r) * CH + lane * 4;
    asm volatile("red.global.add.v4.f32 [%0], {%1, %2, %3, %4};"
                 :: "l"(a), "f"(v.x), "f"(v.y), "f"(v.z), "f"(v.w) : "memory");
    if (lane == 0) {
        float* c = &g_cnt[(size_t)dst * NR + r];
        asm volatile("red.global.add.f32 [%0], %1;" :: "l"(c), "f"(1.0f) : "memory");
    }
}

// ---------------- kernel 3: cnt -> 1/max(cnt,1) ----------------
__global__ void k_inv() {
    int i = blockIdx.x * blockDim.x + threadIdx.x;
    if (i < NT * NR) g_cnt[i] = 1.0f / fmaxf(g_cnt[i], 1.0f);
}

// ---------------- kernel 4: bf16x3 GEMM, register-reused pairing ----------------
// BM=128, BN=128, 8 warps (4m x 2n), warp tile m32n64.
// SMEM row = [hi k0..15 (32B)][lo (32B)], pitch 80 -> conflict-free ldmatrix.
#define PITCH 80
#define SM_ABUF (128 * PITCH)    // 10240
#define SM_BBUF (128 * PITCH)    // 10240
#define SM_TOT  (2 * SM_ABUF + 2 * SM_BBUF)   // 40960

__global__ void __launch_bounds__(256, 2) k_gemm_mma(const float* __restrict__ x_target,
                                                     const int* __restrict__ tgt_type,
                                                     const float* __restrict__ root_b,
                                                     float* __restrict__ out) {
    __shared__ __align__(16) char smem[SM_TOT];
    const uint32_t sb = smem_u32(smem);
    const int tid = threadIdx.x;
    const int lane = tid & 31;
    const int wid = tid >> 5;
    const int wm = wid >> 1;      // 0..3
    const int wn = wid & 1;       // 0..1
    const int t0 = blockIdx.x * 128;

    // ---- fill roles: 2 threads per row, each 8 orig-k ----
    const int arow = tid >> 1;
    const int h    = tid & 1;
    const int t = t0 + arow;
    const bool rv = (t < NT);
    const int myty = rv ? tgt_type[t] : -1;
    const float* xrow = x_target + (size_t)t * CH;

    float acc[2][8][4];
    #pragma unroll
    for (int m = 0; m < 2; m++)
        #pragma unroll
        for (int n = 0; n < 8; n++)
            #pragma unroll
            for (int j = 0; j < 4; j++) acc[m][n][j] = 0.f;

    float av[8];
    auto loadA = [&](int i) {
        const int k0 = i * 16;
        const int kb = (k0 & 127) + h * 8;
        if (k0 < KREL) {
            const int rblk = k0 >> 7;
            if (rv) {
                const size_t base = (size_t)t * NR + rblk;
                const float inv = g_cnt[base];
                const float4* p = reinterpret_cast<const float4*>(g_agg + base * CH + kb);
                float4 v0 = p[0], v1 = p[1];
                av[0] = v0.x * inv; av[1] = v0.y * inv; av[2] = v0.z * inv; av[3] = v0.w * inv;
                av[4] = v1.x * inv; av[5] = v1.y * inv; av[6] = v1.z * inv; av[7] = v1.w * inv;
            } else {
                #pragma unroll
                for (int j = 0; j < 8; j++) av[j] = 0.f;
            }
        } else {
            const int rblk = (k0 - KREL) >> 7;
            if (rv && myty == rblk) {
                const float4* p = reinterpret_cast<const float4*>(xrow + kb);
                float4 v0 = p[0], v1 = p[1];
                av[0] = v0.x; av[1] = v0.y; av[2] = v0.z; av[3] = v0.w;
                av[4] = v1.x; av[5] = v1.y; av[6] = v1.z; av[7] = v1.w;
            } else {
                #pragma unroll
                for (int j = 0; j < 8; j++) av[j] = 0.f;
            }
        }
    };

    // B fill via cp.async: 2 threads/row, thread h copies its 32B (bh or bl)
    auto issueB = [&](int i, int b) {
        uint32_t dst = sb + 2 * SM_ABUF + b * SM_BBUF + arow * PITCH + h * 32;
        const char* src = reinterpret_cast<const char*>(
            g_B2 + ((size_t)arow * NITER + i) * 16 + h * 8);
        cpasync16(dst, src);
        cpasync16(dst + 16, src + 16);
        CP_COMMIT();
    };

    issueB(0, 0);
    loadA(0);

    // ldmatrix address components
    const int a_rb = wm * 32 + (lane & 15);
    const int a_cb = (lane >> 4) * 16;
    const int b_rb = wn * 64 + ((lane >> 4) << 3) + (lane & 7);
    const int b_cb = ((lane >> 3) & 1) * 16;

    for (int i = 0; i < NITER; i++) {
        const int b = i & 1;
        char* Ab = smem + b * SM_ABUF;

        CP_WAIT0();   // B(i) landed

        // ---- store A(i): split 8 floats into hi/lo 16B each ----
        {
            uint16_t hh[8], ll[8];
            #pragma unroll
            for (int j = 0; j < 8; j++) split2(av[j], hh[j], ll[j]);
            uint4 hp = make_uint4((uint32_t)hh[0] | ((uint32_t)hh[1] << 16),
                                  (uint32_t)hh[2] | ((uint32_t)hh[3] << 16),
                                  (uint32_t)hh[4] | ((uint32_t)hh[5] << 16),
                                  (uint32_t)hh[6] | ((uint32_t)hh[7] << 16));
            uint4 lp = make_uint4((uint32_t)ll[0] | ((uint32_t)ll[1] << 16),
                                  (uint32_t)ll[2] | ((uint32_t)ll[3] << 16),
                                  (uint32_t)ll[4] | ((uint32_t)ll[5] << 16),
                                  (uint32_t)ll[6] | ((uint32_t)ll[7] << 16));
            char* rb = Ab + arow * PITCH + h * 16;
            *reinterpret_cast<uint4*>(rb)      = hp;
            *reinterpret_cast<uint4*>(rb + 32) = lp;
        }
        __syncthreads();

        if (i + 1 < NITER) { issueB(i + 1, b ^ 1); loadA(i + 1); }

        // ---- compute: 3-term pairing with fragment reuse ----
        const uint32_t Au = sb + b * SM_ABUF;
        const uint32_t Bu = sb + 2 * SM_ABUF + b * SM_BBUF;
        uint32_t ah[2][4], al[2][4];
        #pragma unroll
        for (int mt = 0; mt < 2; mt++) {
            uint32_t aaddr = Au + (a_rb + mt * 16) * PITCH + a_cb;
            ldsm4(ah[mt], aaddr);
            ldsm4(al[mt], aaddr + 32);
        }
        #pragma unroll
        for (int nt = 0; nt < 4; nt++) {
            uint32_t bh[4], bl[4];
            uint32_t baddr = Bu + (b_rb + nt * 16) * PITCH + b_cb;
            ldsm4(bh, baddr);
            ldsm4(bl, baddr + 32);
            #pragma unroll
            for (int mt = 0; mt < 2; mt++) {
                mma16816(acc[mt][2 * nt],     ah[mt], &bh[0]);
                mma16816(acc[mt][2 * nt + 1], ah[mt], &bh[2]);
                mma16816(acc[mt][2 * nt],     al[mt], &bh[0]);
                mma16816(acc[mt][2 * nt + 1], al[mt], &bh[2]);
                mma16816(acc[mt][2 * nt],     ah[mt], &bl[0]);
                mma16816(acc[mt][2 * nt + 1], ah[mt], &bl[2]);
            }
        }
        __syncthreads();
    }

    // ---- epilogue: per-type bias + store ----
    const int g  = lane >> 2;
    const int tg = lane & 3;
    #pragma unroll
    for (int mt = 0; mt < 2; mt++) {
        const int r0 = t0 + wm * 32 + mt * 16 + g;
        const int r1 = r0 + 8;
        const bool v0 = (r0 < NT), v1 = (r1 < NT);
        const int ty0 = v0 ? tgt_type[r0] : 0;
        const int ty1 = v1 ? tgt_type[r1] : 0;
        const float* rb0 = root_b + (size_t)ty0 * CH;
        const float* rb1 = root_b + (size_t)ty1 * CH;
        #pragma unroll
        for (int j = 0; j < 8; j++) {
            const int col = wn * 64 + j * 8 + tg * 2;
            if (v0) {
                float2 bb = *reinterpret_cast<const float2*>(rb0 + col);
                float2 w = make_float2(acc[mt][j][0] + bb.x, acc[mt][j][1] + bb.y);
                *reinterpret_cast<float2*>(out + (size_t)r0 * CH + col) = w;
            }
            if (v1) {
                float2 bb = *reinterpret_cast<const float2*>(rb1 + col);
                float2 w = make_float2(acc[mt][j][2] + bb.x, acc[mt][j][3] + bb.y);
                *reinterpret_cast<float2*>(out + (size_t)r1 * CH + col) = w;
            }
        }
    }
}

// ---------------- launch ----------------
extern "C" void kernel_launch(void* const* d_in, const int* in_sizes, int n_in,
                              void* d_out, int out_size) {
    const float* x_src     = (const float*)d_in[0];
    const float* x_target  = (const float*)d_in[1];
    const float* rel_w     = (const float*)d_in[2];
    const float* root_w    = (const float*)d_in[3];
    const float* root_b    = (const float*)d_in[4];
    const int*   edge_src  = (const int*)d_in[5];
    const int*   edge_dst  = (const int*)d_in[6];
    const int*   edge_type = (const int*)d_in[7];
    const int*   tgt_type  = (const int*)d_in[8];
    float* out = (float*)d_out;

    (void)in_sizes; (void)n_in; (void)out_size;

    {
        size_t n4 = ((size_t)NT * NR * CH) / 4;
        int blocks = (int)((n4 + 255) / 256);
        k_init<<<blocks, 256>>>(rel_w, root_w);
    }
    k_scatter<<<(NE + 7) / 8, 256>>>(x_src, edge_src, edge_dst, edge_type);
    k_inv<<<(NT * NR + 255) / 256, 256>>>();
    k_gemm_mma<<<(NT + 127) / 128, 256>>>(x_target, tgt_type, root_b, out);
}